// round 8
// baseline (speedup 1.0000x reference)
#include <cuda_runtime.h>
#include <cuda_bf16.h>
#include <cstdint>

#define BB 2
#define HH 16
#define SS 2048
#define DD 64
#define BH (BB*HH)
#define SCALE 0.125f
#define LOG2E 1.4426950408889634f

static __device__ __align__(16) uint32_t g_mbits[(size_t)BB * SS * SS / 32];  // 1MB bit mask

// ---------------------------------------------------------------------------
// helpers
// ---------------------------------------------------------------------------
__device__ __forceinline__ float ex2(float x) {
    float r;
    asm("ex2.approx.f32 %0, %1;" : "=f"(r) : "f"(x));
    return r;
}
// pack (a,b) -> bf16x2 hi part h (a in low half) and bf16x2 residual l
__device__ __forceinline__ void pack_hl(float a, float b, uint32_t& h, uint32_t& l) {
    asm("cvt.rn.bf16x2.f32 %0, %1, %2;" : "=r"(h) : "f"(b), "f"(a));
    float ha = __uint_as_float(h << 16);
    float hb = __uint_as_float(h & 0xffff0000u);
    asm("cvt.rn.bf16x2.f32 %0, %1, %2;" : "=r"(l) : "f"(b - hb), "f"(a - ha));
}

// mma.sync m16n8k16 row.col f32.bf16.bf16.f32 — D accumulates in place
#define MMA(d, a, b0v, b1v) \
    asm volatile("mma.sync.aligned.m16n8k16.row.col.f32.bf16.bf16.f32 " \
        "{%0,%1,%2,%3}, {%4,%5,%6,%7}, {%8,%9}, {%0,%1,%2,%3};" \
        : "+f"((d)[0]), "+f"((d)[1]), "+f"((d)[2]), "+f"((d)[3]) \
        : "r"((a)[0]), "r"((a)[1]), "r"((a)[2]), "r"((a)[3]), "r"(b0v), "r"(b1v))

// smem layout (bytes).
// K tiles: [key 128][d 64] bf16, row stride 144B. hi/lo.
// V tiles (transposed): [d 64][key 128] bf16, row stride 272B. hi/lo.
// inv[128] fp32 at the end.
#define SM_KH 0
#define SM_KL 18432
#define SM_VH 36864
#define SM_VL 54272
#define SM_INV 71680
#define SMEM_BYTES 72192

// ---------------------------------------------------------------------------
// Kernel 0: bit-pack the int32 mask. word w covers elements [w*32, w*32+32)
// ---------------------------------------------------------------------------
__global__ __launch_bounds__(256)
void mask_pack(const int* __restrict__ mask)
{
    const size_t w = (size_t)blockIdx.x * 256 + threadIdx.x;   // 262144 words
    const int4* p = (const int4*)mask + w * 8;
    uint32_t bits = 0;
    #pragma unroll
    for (int j = 0; j < 8; j++) {
        int4 x = p[j];
        bits |= (x.x ? 1u : 0u) << (j * 4 + 0);
        bits |= (x.y ? 1u : 0u) << (j * 4 + 1);
        bits |= (x.z ? 1u : 0u) << (j * 4 + 2);
        bits |= (x.w ? 1u : 0u) << (j * 4 + 3);
    }
    g_mbits[w] = bits;
}

// ---------------------------------------------------------------------------
// device routines
// ---------------------------------------------------------------------------
__device__ __forceinline__ void load_q_frags(const float* __restrict__ q,
                                             int bh, int r0, int r8, int t,
                                             uint32_t (&qh)[4][4], uint32_t (&ql)[4][4])
{
    const float* qp = q + (size_t)bh * SS * DD;
    const float sc = SCALE * LOG2E;
    #pragma unroll
    for (int ks = 0; ks < 4; ks++) {
        const int c = ks * 16 + t * 2;
        float2 x0 = *(const float2*)(qp + (size_t)r0 * DD + c);
        float2 x1 = *(const float2*)(qp + (size_t)r8 * DD + c);
        float2 x2 = *(const float2*)(qp + (size_t)r0 * DD + c + 8);
        float2 x3 = *(const float2*)(qp + (size_t)r8 * DD + c + 8);
        pack_hl(x0.x * sc, x0.y * sc, qh[ks][0], ql[ks][0]);
        pack_hl(x1.x * sc, x1.y * sc, qh[ks][1], ql[ks][1]);
        pack_hl(x2.x * sc, x2.y * sc, qh[ks][2], ql[ks][2]);
        pack_hl(x3.x * sc, x3.y * sc, qh[ks][3], ql[ks][3]);
    }
}

__device__ __forceinline__ void stage_k_tile(char* smem, const float* __restrict__ k,
                                             int bh, int n0, int tid)
{
    const int r  = tid >> 1;
    const int c0 = (tid & 1) * 32;
    const float* kp = k + ((size_t)bh * SS + n0 + r) * DD + c0;
    #pragma unroll
    for (int i = 0; i < 8; i++) {
        float4 f = *(const float4*)(kp + i * 4);
        uint32_t h01, l01, h23, l23;
        pack_hl(f.x, f.y, h01, l01);
        pack_hl(f.z, f.w, h23, l23);
        const int off = r * 144 + (c0 + i * 4) * 2;
        *(uint2*)(smem + SM_KH + off) = make_uint2(h01, h23);
        *(uint2*)(smem + SM_KL + off) = make_uint2(l01, l23);
    }
}

__device__ __forceinline__ void stage_v_tile(char* smem, const float* __restrict__ v,
                                             int bh, int n0, int tid)
{
    const int kp2 = tid >> 2;            // key pair 0..63
    const int c0v = (tid & 3) * 16;      // d range
    const float* vp = v + ((size_t)bh * SS + n0 + 2 * kp2) * DD + c0v;
    #pragma unroll
    for (int i = 0; i < 4; i++) {
        float4 a0 = *(const float4*)(vp + i * 4);
        float4 a1 = *(const float4*)(vp + DD + i * 4);
        const float e0[4] = {a0.x, a0.y, a0.z, a0.w};
        const float e1[4] = {a1.x, a1.y, a1.z, a1.w};
        #pragma unroll
        for (int j = 0; j < 4; j++) {
            const int d = c0v + i * 4 + j;
            uint32_t h, l;
            pack_hl(e0[j], e1[j], h, l);
            *(uint32_t*)(smem + SM_VH + d * 272 + kp2 * 4) = h;
            *(uint32_t*)(smem + SM_VL + d * 272 + kp2 * 4) = l;
        }
    }
}

// ---------------------------------------------------------------------------
// Flash kernel: e = exp(masked score) -> atten (unnormalized), O = sum e*V,
//               out = O/sum; tail: atten *= 1/sum (coalesced streaming).
// ---------------------------------------------------------------------------
__global__ void __launch_bounds__(256, 2)
sdpa_flash(const float* __restrict__ q, const float* __restrict__ k,
           const float* __restrict__ v,
           float* __restrict__ atten, float* __restrict__ out)
{
    extern __shared__ char smem[];
    const int tid  = threadIdx.x;
    const int w    = tid >> 5;
    const int lane = tid & 31;
    const int g    = lane >> 2;
    const int t    = lane & 3;
    const int bh   = blockIdx.y;
    const int b    = bh / HH;
    const int q0   = blockIdx.x * 128;
    const int r0   = q0 + w * 16 + g;
    const int r8   = r0 + 8;

    const size_t mb0 = ((size_t)b * SS + r0) * 64;
    const size_t mb8 = ((size_t)b * SS + r8) * 64;
    float* arow_g  = atten + ((size_t)bh * SS + r0) * SS;
    float* arow_g8 = atten + ((size_t)bh * SS + r8) * SS;

    uint32_t qh[4][4], ql[4][4];
    load_q_frags(q, bh, r0, r8, t, qh, ql);

    float sum_g = 0.0f, sum_g8 = 0.0f;
    float o[8][4];
    #pragma unroll
    for (int nd = 0; nd < 8; nd++)
        #pragma unroll
        for (int i = 0; i < 4; i++) o[nd][i] = 0.0f;

    for (int kt = 0; kt < 16; kt++) {
        const int n0 = kt * 128;
        __syncthreads();
        stage_k_tile(smem, k, bh, n0, tid);
        stage_v_tile(smem, v, bh, n0, tid);
        __syncthreads();

        uint4 mg = *(const uint4*)(g_mbits + mb0 + n0 / 32);
        uint4 m8 = *(const uint4*)(g_mbits + mb8 + n0 / 32);
        const uint32_t* mgw = (const uint32_t*)&mg;
        const uint32_t* m8w = (const uint32_t*)&m8;

        // process the 128-key tile in two 64-key halves (register economy)
        #pragma unroll
        for (int h = 0; h < 2; h++) {
            float s[8][4];
            #pragma unroll
            for (int nt = 0; nt < 8; nt++)
                #pragma unroll
                for (int i = 0; i < 4; i++) s[nt][i] = 0.0f;

            // QK for this half
            #pragma unroll
            for (int ks = 0; ks < 4; ks++) {
                #pragma unroll
                for (int pass = 0; pass < 3; pass++) {
                    const uint32_t* A = (pass == 2) ? ql[ks] : qh[ks];
                    const int bb = (pass == 1) ? SM_KL : SM_KH;
                    #pragma unroll
                    for (int nt = 0; nt < 8; nt++) {
                        const char* ad = smem + bb + ((h * 8 + nt) * 8 + g) * 144 + ks * 32 + t * 4;
                        uint32_t b0 = *(const uint32_t*)ad;
                        uint32_t b1 = *(const uint32_t*)(ad + 16);
                        MMA(s[nt], A, b0, b1);
                    }
                }
            }

            // epilogue + AV for this half
            #pragma unroll
            for (int kap = 0; kap < 4; kap++) {
                uint32_t ah[4], al[4];
                #pragma unroll
                for (int i = 0; i < 2; i++) {
                    const int nt  = kap * 2 + i;       // within half
                    const int ntg = h * 8 + nt;        // within 128-key tile
                    const uint32_t wg = mgw[ntg >> 2] >> ((ntg & 3) * 8 + t * 2);
                    const uint32_t w8 = m8w[ntg >> 2] >> ((ntg & 3) * 8 + t * 2);
                    const float e0 = (wg      & 1) ? 0.0f : ex2(s[nt][0]);
                    const float e1 = (wg >> 1 & 1) ? 0.0f : ex2(s[nt][1]);
                    const float e2 = (w8      & 1) ? 0.0f : ex2(s[nt][2]);
                    const float e3 = (w8 >> 1 & 1) ? 0.0f : ex2(s[nt][3]);
                    sum_g  += e0 + e1;
                    sum_g8 += e2 + e3;
                    const int c = n0 + ntg * 8 + t * 2;
                    *(float2*)(arow_g  + c) = make_float2(e0, e1);
                    *(float2*)(arow_g8 + c) = make_float2(e2, e3);
                    pack_hl(e0, e1, ah[i*2+0], al[i*2+0]);
                    pack_hl(e2, e3, ah[i*2+1], al[i*2+1]);
                }
                #pragma unroll
                for (int nd = 0; nd < 8; nd++) {
                    const int vbase = (nd * 8 + g) * 272 + (h * 4 + kap) * 32 + t * 4;
                    const char* vh = smem + SM_VH + vbase;
                    const char* vl = smem + SM_VL + vbase;
                    uint32_t bh0 = *(const uint32_t*)vh;
                    uint32_t bh1 = *(const uint32_t*)(vh + 16);
                    uint32_t bl0 = *(const uint32_t*)vl;
                    uint32_t bl1 = *(const uint32_t*)(vl + 16);
                    MMA(o[nd], ah, bh0, bh1);
                    MMA(o[nd], ah, bl0, bl1);
                    MMA(o[nd], al, bh0, bh1);
                }
            }
        }
    }

    // reduce row sums across the 4 t-lanes
    sum_g  += __shfl_xor_sync(0xffffffffu, sum_g, 1);
    sum_g  += __shfl_xor_sync(0xffffffffu, sum_g, 2);
    sum_g8 += __shfl_xor_sync(0xffffffffu, sum_g8, 1);
    sum_g8 += __shfl_xor_sync(0xffffffffu, sum_g8, 2);
    const float inv_g  = 1.0f / sum_g;
    const float inv_g8 = 1.0f / sum_g8;

    // write out = O/sum
    float* orow_g  = out + ((size_t)bh * SS + r0) * DD;
    float* orow_g8 = out + ((size_t)bh * SS + r8) * DD;
    #pragma unroll
    for (int nd = 0; nd < 8; nd++) {
        *(float2*)(orow_g  + nd * 8 + t * 2) = make_float2(o[nd][0] * inv_g,  o[nd][1] * inv_g);
        *(float2*)(orow_g8 + nd * 8 + t * 2) = make_float2(o[nd][2] * inv_g8, o[nd][3] * inv_g8);
    }

    // ---- tail: normalize this CTA's atten rows (coalesced streaming) ----
    float* sinv = (float*)(smem + SM_INV);
    __syncthreads();          // smem tiles done being read; safe to overlay inv
    if (t == 0) {
        sinv[w * 16 + g]     = inv_g;
        sinv[w * 16 + g + 8] = inv_g8;
    }
    __syncthreads();          // inv visible + e-writes globally ordered in CTA

    float* abase = atten + ((size_t)bh * SS + q0) * SS;
    #pragma unroll 2
    for (int i = tid; i < 128 * (SS / 4); i += 256) {
        const int row = i >> 9;             // SS/4 = 512 float4 per row
        const int c4  = i & 511;
        const float inv = sinv[row];
        float4* p = (float4*)(abase + (size_t)row * SS) + c4;
        float4 x = *p;
        x.x *= inv; x.y *= inv; x.z *= inv; x.w *= inv;
        *p = x;
    }
}

// ---------------------------------------------------------------------------
extern "C" void kernel_launch(void* const* d_in, const int* in_sizes, int n_in,
                              void* d_out, int out_size)
{
    const float* q = (const float*)d_in[0];
    const float* k = (const float*)d_in[1];
    const float* v = (const float*)d_in[2];
    const int*   mask = (const int*)d_in[3];

    float* out   = (float*)d_out;                 // [B,H,S,D]
    float* atten = out + (size_t)BH * SS * DD;    // [B,H,S,S]

    cudaFuncSetAttribute(sdpa_flash, cudaFuncAttributeMaxDynamicSharedMemorySize, SMEM_BYTES);

    dim3 grid(SS / 128, BH);
    mask_pack<<<1024, 256>>>(mask);
    sdpa_flash<<<grid, 256, SMEM_BYTES>>>(q, k, v, atten, out);
    (void)in_sizes; (void)n_in; (void)out_size;
}

// round 9
// speedup vs baseline: 1.2011x; 1.2011x over previous
#include <cuda_runtime.h>
#include <cuda_bf16.h>
#include <cstdint>

#define BB 2
#define HH 16
#define SS 2048
#define DD 64
#define BH (BB*HH)
#define SCALE 0.125f
#define LOG2E 1.4426950408889634f

static __device__ float g_row_s[BH * SS];
static __device__ __align__(16) uint32_t g_mbits[(size_t)BB * SS * SS / 32];  // 1MB bit mask

// ---------------------------------------------------------------------------
// helpers
// ---------------------------------------------------------------------------
__device__ __forceinline__ float ex2(float x) {
    float r;
    asm("ex2.approx.f32 %0, %1;" : "=f"(r) : "f"(x));
    return r;
}
// pack (a,b) -> bf16x2 hi part h (a in low half) and bf16x2 residual l
__device__ __forceinline__ void pack_hl(float a, float b, uint32_t& h, uint32_t& l) {
    asm("cvt.rn.bf16x2.f32 %0, %1, %2;" : "=r"(h) : "f"(b), "f"(a));
    float ha = __uint_as_float(h << 16);
    float hb = __uint_as_float(h & 0xffff0000u);
    asm("cvt.rn.bf16x2.f32 %0, %1, %2;" : "=r"(l) : "f"(b - hb), "f"(a - ha));
}

// mma.sync m16n8k16 row.col f32.bf16.bf16.f32 — D accumulates in place
#define MMA(d, a, b0v, b1v) \
    asm volatile("mma.sync.aligned.m16n8k16.row.col.f32.bf16.bf16.f32 " \
        "{%0,%1,%2,%3}, {%4,%5,%6,%7}, {%8,%9}, {%0,%1,%2,%3};" \
        : "+f"((d)[0]), "+f"((d)[1]), "+f"((d)[2]), "+f"((d)[3]) \
        : "r"((a)[0]), "r"((a)[1]), "r"((a)[2]), "r"((a)[3]), "r"(b0v), "r"(b1v))

// smem layout (bytes).
// K tiles: [key 128][d 64] bf16, row stride 144B. hi/lo.
// V tiles (transposed): [d 64][key 128] bf16, row stride 272B. hi/lo.
#define SM_KH 0
#define SM_KL 18432
#define SM_VH 36864
#define SM_VL 54272
#define SMEM_BYTES 71680

// ---------------------------------------------------------------------------
// Kernel 0: bit-pack the int32 mask. word w covers elements [w*32, w*32+32)
// ---------------------------------------------------------------------------
__global__ __launch_bounds__(256)
void mask_pack(const int* __restrict__ mask)
{
    const size_t w = (size_t)blockIdx.x * 256 + threadIdx.x;   // 262144 words
    const int4* p = (const int4*)mask + w * 8;
    uint32_t bits = 0;
    #pragma unroll
    for (int j = 0; j < 8; j++) {
        int4 x = p[j];
        bits |= (x.x ? 1u : 0u) << (j * 4 + 0);
        bits |= (x.y ? 1u : 0u) << (j * 4 + 1);
        bits |= (x.z ? 1u : 0u) << (j * 4 + 2);
        bits |= (x.w ? 1u : 0u) << (j * 4 + 3);
    }
    g_mbits[w] = bits;
}

// ---------------------------------------------------------------------------
// device routines
// ---------------------------------------------------------------------------
__device__ __forceinline__ void load_q_frags(const float* __restrict__ q,
                                             int bh, int r0, int r8, int t,
                                             uint32_t (&qh)[4][4], uint32_t (&ql)[4][4])
{
    const float* qp = q + (size_t)bh * SS * DD;
    const float sc = SCALE * LOG2E;
    #pragma unroll
    for (int ks = 0; ks < 4; ks++) {
        const int c = ks * 16 + t * 2;
        float2 x0 = *(const float2*)(qp + (size_t)r0 * DD + c);
        float2 x1 = *(const float2*)(qp + (size_t)r8 * DD + c);
        float2 x2 = *(const float2*)(qp + (size_t)r0 * DD + c + 8);
        float2 x3 = *(const float2*)(qp + (size_t)r8 * DD + c + 8);
        pack_hl(x0.x * sc, x0.y * sc, qh[ks][0], ql[ks][0]);
        pack_hl(x1.x * sc, x1.y * sc, qh[ks][1], ql[ks][1]);
        pack_hl(x2.x * sc, x2.y * sc, qh[ks][2], ql[ks][2]);
        pack_hl(x3.x * sc, x3.y * sc, qh[ks][3], ql[ks][3]);
    }
}

__device__ __forceinline__ void stage_k_tile(char* smem, const float* __restrict__ k,
                                             int bh, int n0, int tid)
{
    const int r  = tid >> 1;
    const int c0 = (tid & 1) * 32;
    const float* kp = k + ((size_t)bh * SS + n0 + r) * DD + c0;
    #pragma unroll
    for (int i = 0; i < 8; i++) {
        float4 f = *(const float4*)(kp + i * 4);
        uint32_t h01, l01, h23, l23;
        pack_hl(f.x, f.y, h01, l01);
        pack_hl(f.z, f.w, h23, l23);
        const int off = r * 144 + (c0 + i * 4) * 2;
        *(uint2*)(smem + SM_KH + off) = make_uint2(h01, h23);
        *(uint2*)(smem + SM_KL + off) = make_uint2(l01, l23);
    }
}

__device__ __forceinline__ void stage_v_tile(char* smem, const float* __restrict__ v,
                                             int bh, int n0, int tid)
{
    const int kp2 = tid >> 2;            // key pair 0..63
    const int c0v = (tid & 3) * 16;      // d range
    const float* vp = v + ((size_t)bh * SS + n0 + 2 * kp2) * DD + c0v;
    #pragma unroll
    for (int i = 0; i < 4; i++) {
        float4 a0 = *(const float4*)(vp + i * 4);
        float4 a1 = *(const float4*)(vp + DD + i * 4);
        const float e0[4] = {a0.x, a0.y, a0.z, a0.w};
        const float e1[4] = {a1.x, a1.y, a1.z, a1.w};
        #pragma unroll
        for (int j = 0; j < 4; j++) {
            const int d = c0v + i * 4 + j;
            uint32_t h, l;
            pack_hl(e0[j], e1[j], h, l);
            *(uint32_t*)(smem + SM_VH + d * 272 + kp2 * 4) = h;
            *(uint32_t*)(smem + SM_VL + d * 272 + kp2 * 4) = l;
        }
    }
}

// ---------------------------------------------------------------------------
// Kernel 1: flash pass. e = exp(masked score) -> atten (unnormalized, .cs),
//           O = sum e*V, out = O/sum, g_row_s = sum.
// ---------------------------------------------------------------------------
__global__ void __launch_bounds__(256, 2)
sdpa_flash(const float* __restrict__ q, const float* __restrict__ k,
           const float* __restrict__ v,
           float* __restrict__ atten, float* __restrict__ out)
{
    extern __shared__ char smem[];
    const int tid  = threadIdx.x;
    const int w    = tid >> 5;
    const int lane = tid & 31;
    const int g    = lane >> 2;
    const int t    = lane & 3;
    const int bh   = blockIdx.y;
    const int b    = bh / HH;
    const int q0   = blockIdx.x * 128;
    const int r0   = q0 + w * 16 + g;
    const int r8   = r0 + 8;

    const size_t mb0 = ((size_t)b * SS + r0) * 64;
    const size_t mb8 = ((size_t)b * SS + r8) * 64;
    float* arow_g  = atten + ((size_t)bh * SS + r0) * SS;
    float* arow_g8 = atten + ((size_t)bh * SS + r8) * SS;

    uint32_t qh[4][4], ql[4][4];
    load_q_frags(q, bh, r0, r8, t, qh, ql);

    float sum_g = 0.0f, sum_g8 = 0.0f;
    float o[8][4];
    #pragma unroll
    for (int nd = 0; nd < 8; nd++)
        #pragma unroll
        for (int i = 0; i < 4; i++) o[nd][i] = 0.0f;

    for (int kt = 0; kt < 16; kt++) {
        const int n0 = kt * 128;
        __syncthreads();
        stage_k_tile(smem, k, bh, n0, tid);
        stage_v_tile(smem, v, bh, n0, tid);
        __syncthreads();

        uint4 mg = *(const uint4*)(g_mbits + mb0 + n0 / 32);
        uint4 m8 = *(const uint4*)(g_mbits + mb8 + n0 / 32);
        const uint32_t* mgw = (const uint32_t*)&mg;
        const uint32_t* m8w = (const uint32_t*)&m8;

        // process the 128-key tile in two 64-key halves (register economy)
        #pragma unroll
        for (int h = 0; h < 2; h++) {
            float s[8][4];
            #pragma unroll
            for (int nt = 0; nt < 8; nt++)
                #pragma unroll
                for (int i = 0; i < 4; i++) s[nt][i] = 0.0f;

            // QK for this half
            #pragma unroll
            for (int ks = 0; ks < 4; ks++) {
                #pragma unroll
                for (int pass = 0; pass < 3; pass++) {
                    const uint32_t* A = (pass == 2) ? ql[ks] : qh[ks];
                    const int bb = (pass == 1) ? SM_KL : SM_KH;
                    #pragma unroll
                    for (int nt = 0; nt < 8; nt++) {
                        const char* ad = smem + bb + ((h * 8 + nt) * 8 + g) * 144 + ks * 32 + t * 4;
                        uint32_t b0 = *(const uint32_t*)ad;
                        uint32_t b1 = *(const uint32_t*)(ad + 16);
                        MMA(s[nt], A, b0, b1);
                    }
                }
            }

            // epilogue + AV for this half
            #pragma unroll
            for (int kap = 0; kap < 4; kap++) {
                uint32_t ah[4], al[4];
                #pragma unroll
                for (int i = 0; i < 2; i++) {
                    const int nt  = kap * 2 + i;       // within half
                    const int ntg = h * 8 + nt;        // within 128-key tile
                    const uint32_t wg = mgw[ntg >> 2] >> ((ntg & 3) * 8 + t * 2);
                    const uint32_t w8 = m8w[ntg >> 2] >> ((ntg & 3) * 8 + t * 2);
                    const float e0 = (wg      & 1) ? 0.0f : ex2(s[nt][0]);
                    const float e1 = (wg >> 1 & 1) ? 0.0f : ex2(s[nt][1]);
                    const float e2 = (w8      & 1) ? 0.0f : ex2(s[nt][2]);
                    const float e3 = (w8 >> 1 & 1) ? 0.0f : ex2(s[nt][3]);
                    sum_g  += e0 + e1;
                    sum_g8 += e2 + e3;
                    const int c = n0 + ntg * 8 + t * 2;
                    __stcs((float2*)(arow_g  + c), make_float2(e0, e1));
                    __stcs((float2*)(arow_g8 + c), make_float2(e2, e3));
                    pack_hl(e0, e1, ah[i*2+0], al[i*2+0]);
                    pack_hl(e2, e3, ah[i*2+1], al[i*2+1]);
                }
                #pragma unroll
                for (int nd = 0; nd < 8; nd++) {
                    const int vbase = (nd * 8 + g) * 272 + (h * 4 + kap) * 32 + t * 4;
                    const char* vh = smem + SM_VH + vbase;
                    const char* vl = smem + SM_VL + vbase;
                    uint32_t bh0 = *(const uint32_t*)vh;
                    uint32_t bh1 = *(const uint32_t*)(vh + 16);
                    uint32_t bl0 = *(const uint32_t*)vl;
                    uint32_t bl1 = *(const uint32_t*)(vl + 16);
                    MMA(o[nd], ah, bh0, bh1);
                    MMA(o[nd], ah, bl0, bl1);
                    MMA(o[nd], al, bh0, bh1);
                }
            }
        }
    }

    // reduce row sums across the 4 t-lanes
    sum_g  += __shfl_xor_sync(0xffffffffu, sum_g, 1);
    sum_g  += __shfl_xor_sync(0xffffffffu, sum_g, 2);
    sum_g8 += __shfl_xor_sync(0xffffffffu, sum_g8, 1);
    sum_g8 += __shfl_xor_sync(0xffffffffu, sum_g8, 2);
    const float inv_g  = 1.0f / sum_g;
    const float inv_g8 = 1.0f / sum_g8;
    if (t == 0) {
        g_row_s[bh * SS + r0] = sum_g;
        g_row_s[bh * SS + r8] = sum_g8;
    }

    float* orow_g  = out + ((size_t)bh * SS + r0) * DD;
    float* orow_g8 = out + ((size_t)bh * SS + r8) * DD;
    #pragma unroll
    for (int nd = 0; nd < 8; nd++) {
        *(float2*)(orow_g  + nd * 8 + t * 2) = make_float2(o[nd][0] * inv_g,  o[nd][1] * inv_g);
        *(float2*)(orow_g8 + nd * 8 + t * 2) = make_float2(o[nd][2] * inv_g8, o[nd][3] * inv_g8);
    }
}

// ---------------------------------------------------------------------------
// Kernel 2: atten[row, :] *= 1/g_row_s[row]. One block per row, streaming.
// ---------------------------------------------------------------------------
__global__ void __launch_bounds__(256)
atten_norm(float* __restrict__ atten)
{
    const int row = blockIdx.x;                 // 0 .. BH*SS-1
    const float inv = 1.0f / g_row_s[row];
    float4* p = (float4*)(atten + (size_t)row * SS);
    const int i0 = threadIdx.x;
    float4 a = __ldcs(p + i0);
    float4 c = __ldcs(p + i0 + 256);
    a.x *= inv; a.y *= inv; a.z *= inv; a.w *= inv;
    c.x *= inv; c.y *= inv; c.z *= inv; c.w *= inv;
    __stcs(p + i0, a);
    __stcs(p + i0 + 256, c);
}

// ---------------------------------------------------------------------------
extern "C" void kernel_launch(void* const* d_in, const int* in_sizes, int n_in,
                              void* d_out, int out_size)
{
    const float* q = (const float*)d_in[0];
    const float* k = (const float*)d_in[1];
    const float* v = (const float*)d_in[2];
    const int*   mask = (const int*)d_in[3];

    float* out   = (float*)d_out;                 // [B,H,S,D]
    float* atten = out + (size_t)BH * SS * DD;    // [B,H,S,S]

    cudaFuncSetAttribute(sdpa_flash, cudaFuncAttributeMaxDynamicSharedMemorySize, SMEM_BYTES);

    dim3 grid(SS / 128, BH);
    mask_pack<<<1024, 256>>>(mask);
    sdpa_flash<<<grid, 256, SMEM_BYTES>>>(q, k, v, atten, out);
    atten_norm<<<BH * SS, 256>>>(atten);
    (void)in_sizes; (void)n_in; (void)out_size;
}

// round 10
// speedup vs baseline: 1.3850x; 1.1531x over previous
#include <cuda_runtime.h>
#include <cuda_bf16.h>
#include <cstdint>

#define BB 2
#define HH 16
#define SS 2048
#define DD 64
#define BH (BB*HH)
#define SCALE 0.125f
#define LOG2E 1.4426950408889634f

static __device__ float g_row_s[BH * SS];
static __device__ __align__(16) uint32_t g_mbits[(size_t)BB * SS * SS / 32];  // 1MB
// bf16 hi/lo scratch (packed as uint32 = bf16x2). K: [bh][key][d], V: [bh][d][key]
static __device__ __align__(16) uint32_t g_kh[(size_t)BH * SS * DD / 2];
static __device__ __align__(16) uint32_t g_kl[(size_t)BH * SS * DD / 2];
static __device__ __align__(16) uint32_t g_vth[(size_t)BH * SS * DD / 2];
static __device__ __align__(16) uint32_t g_vtl[(size_t)BH * SS * DD / 2];

// ---------------------------------------------------------------------------
// helpers
// ---------------------------------------------------------------------------
__device__ __forceinline__ float ex2(float x) {
    float r;
    asm("ex2.approx.f32 %0, %1;" : "=f"(r) : "f"(x));
    return r;
}
__device__ __forceinline__ void pack_hl(float a, float b, uint32_t& h, uint32_t& l) {
    asm("cvt.rn.bf16x2.f32 %0, %1, %2;" : "=r"(h) : "f"(b), "f"(a));
    float ha = __uint_as_float(h << 16);
    float hb = __uint_as_float(h & 0xffff0000u);
    asm("cvt.rn.bf16x2.f32 %0, %1, %2;" : "=r"(l) : "f"(b - hb), "f"(a - ha));
}
__device__ __forceinline__ uint32_t smem_u32(const void* p) {
    uint32_t a;
    asm("{ .reg .u64 t; cvta.to.shared.u64 t, %1; cvt.u32.u64 %0, t; }"
        : "=r"(a) : "l"(p));
    return a;
}
#define CPA16(dst, src) \
    asm volatile("cp.async.cg.shared.global [%0], [%1], 16;" :: "r"(dst), "l"(src))
#define CPA_COMMIT() asm volatile("cp.async.commit_group;" ::: "memory")
#define CPA_WAIT0()  asm volatile("cp.async.wait_group 0;" ::: "memory")

// mma.sync m16n8k16 row.col f32.bf16.bf16.f32 — D accumulates in place
#define MMA(d, a, b0v, b1v) \
    asm volatile("mma.sync.aligned.m16n8k16.row.col.f32.bf16.bf16.f32 " \
        "{%0,%1,%2,%3}, {%4,%5,%6,%7}, {%8,%9}, {%0,%1,%2,%3};" \
        : "+f"((d)[0]), "+f"((d)[1]), "+f"((d)[2]), "+f"((d)[3]) \
        : "r"((a)[0]), "r"((a)[1]), "r"((a)[2]), "r"((a)[3]), "r"(b0v), "r"(b1v))

// smem: K tiles [key 128][d 64] bf16, row stride 144B; V tiles [d 64][key 128], stride 272B
#define SM_KH 0
#define SM_KL 18432
#define SM_VH 36864
#define SM_VL 54272
#define SMEM_BYTES 71680

// ---------------------------------------------------------------------------
// Kernel 0: bit-pack the int32 mask
// ---------------------------------------------------------------------------
__global__ __launch_bounds__(256)
void mask_pack(const int* __restrict__ mask)
{
    const size_t w = (size_t)blockIdx.x * 256 + threadIdx.x;
    const int4* p = (const int4*)mask + w * 8;
    uint32_t bits = 0;
    #pragma unroll
    for (int j = 0; j < 8; j++) {
        int4 x = p[j];
        bits |= (x.x ? 1u : 0u) << (j * 4 + 0);
        bits |= (x.y ? 1u : 0u) << (j * 4 + 1);
        bits |= (x.z ? 1u : 0u) << (j * 4 + 2);
        bits |= (x.w ? 1u : 0u) << (j * 4 + 3);
    }
    g_mbits[w] = bits;
}

// ---------------------------------------------------------------------------
// Kernel 0b: K -> bf16 hi/lo (natural layout). 8 elements per thread.
// ---------------------------------------------------------------------------
__global__ __launch_bounds__(256)
void conv_k(const float* __restrict__ k)
{
    const size_t i0 = ((size_t)blockIdx.x * 256 + threadIdx.x) * 8;
    float4 a = *(const float4*)(k + i0);
    float4 b = *(const float4*)(k + i0 + 4);
    uint32_t h[4], l[4];
    pack_hl(a.x, a.y, h[0], l[0]);
    pack_hl(a.z, a.w, h[1], l[1]);
    pack_hl(b.x, b.y, h[2], l[2]);
    pack_hl(b.z, b.w, h[3], l[3]);
    *(uint4*)(g_kh + i0 / 2) = make_uint4(h[0], h[1], h[2], h[3]);
    *(uint4*)(g_kl + i0 / 2) = make_uint4(l[0], l[1], l[2], l[3]);
}

// ---------------------------------------------------------------------------
// Kernel 0c: V -> bf16 hi/lo transposed [bh][d][key] via smem tile transpose.
// grid (SS/64, BH), block 256. Tile: 64 keys x 64 d.
// ---------------------------------------------------------------------------
__global__ __launch_bounds__(256)
void conv_vt(const float* __restrict__ v)
{
    __shared__ float ts[64][65];
    const int tid = threadIdx.x;
    const int bh  = blockIdx.y;
    const int n0  = blockIdx.x * 64;

    // load 64x64 fp32 tile coalesced
    const int r  = tid >> 2;
    const int c0 = (tid & 3) * 16;
    const float* vp = v + ((size_t)bh * SS + n0 + r) * DD + c0;
    #pragma unroll
    for (int i = 0; i < 4; i++) {
        float4 f = *(const float4*)(vp + i * 4);
        ts[r][c0 + i*4 + 0] = f.x;
        ts[r][c0 + i*4 + 1] = f.y;
        ts[r][c0 + i*4 + 2] = f.z;
        ts[r][c0 + i*4 + 3] = f.w;
    }
    __syncthreads();

    // write transposed: row = d, 16 keys (8 pairs) per thread
    const int d  = tid >> 2;
    const int kc = (tid & 3) * 16;
    uint32_t h[8], l[8];
    #pragma unroll
    for (int m = 0; m < 8; m++)
        pack_hl(ts[kc + 2*m][d], ts[kc + 2*m + 1][d], h[m], l[m]);
    const size_t o = (((size_t)bh * DD + d) * SS + n0 + kc) / 2;
    *(uint4*)(g_vth + o)     = make_uint4(h[0], h[1], h[2], h[3]);
    *(uint4*)(g_vth + o + 4) = make_uint4(h[4], h[5], h[6], h[7]);
    *(uint4*)(g_vtl + o)     = make_uint4(l[0], l[1], l[2], l[3]);
    *(uint4*)(g_vtl + o + 4) = make_uint4(l[4], l[5], l[6], l[7]);
}

// ---------------------------------------------------------------------------
// Q fragments (hi/lo), scale*log2e folded in
// ---------------------------------------------------------------------------
__device__ __forceinline__ void load_q_frags(const float* __restrict__ q,
                                             int bh, int r0, int r8, int t,
                                             uint32_t (&qh)[4][4], uint32_t (&ql)[4][4])
{
    const float* qp = q + (size_t)bh * SS * DD;
    const float sc = SCALE * LOG2E;
    #pragma unroll
    for (int ks = 0; ks < 4; ks++) {
        const int c = ks * 16 + t * 2;
        float2 x0 = *(const float2*)(qp + (size_t)r0 * DD + c);
        float2 x1 = *(const float2*)(qp + (size_t)r8 * DD + c);
        float2 x2 = *(const float2*)(qp + (size_t)r0 * DD + c + 8);
        float2 x3 = *(const float2*)(qp + (size_t)r8 * DD + c + 8);
        pack_hl(x0.x * sc, x0.y * sc, qh[ks][0], ql[ks][0]);
        pack_hl(x1.x * sc, x1.y * sc, qh[ks][1], ql[ks][1]);
        pack_hl(x2.x * sc, x2.y * sc, qh[ks][2], ql[ks][2]);
        pack_hl(x3.x * sc, x3.y * sc, qh[ks][3], ql[ks][3]);
    }
}

// ---------------------------------------------------------------------------
// Kernel 1: flash. cp.async-staged bf16 tiles; e -> atten (.cs); out = O/sum.
// ---------------------------------------------------------------------------
__global__ void __launch_bounds__(256, 2)
sdpa_flash(const float* __restrict__ q,
           float* __restrict__ atten, float* __restrict__ out)
{
    extern __shared__ char smem[];
    const int tid  = threadIdx.x;
    const int lane = tid & 31;
    const int g    = lane >> 2;
    const int t    = lane & 3;
    const int w    = tid >> 5;
    const int bh   = blockIdx.y;
    const int b    = bh / HH;
    const int q0   = blockIdx.x * 128;
    const int r0   = q0 + w * 16 + g;
    const int r8   = r0 + 8;
    const uint32_t sb = smem_u32(smem);

    const size_t mb0 = ((size_t)b * SS + r0) * 64;
    const size_t mb8 = ((size_t)b * SS + r8) * 64;
    float* arow_g  = atten + ((size_t)bh * SS + r0) * SS;
    float* arow_g8 = atten + ((size_t)bh * SS + r8) * SS;

    uint32_t qh[4][4], ql[4][4];
    load_q_frags(q, bh, r0, r8, t, qh, ql);

    float sum_g = 0.0f, sum_g8 = 0.0f;
    float o[8][4];
    #pragma unroll
    for (int nd = 0; nd < 8; nd++)
        #pragma unroll
        for (int i = 0; i < 4; i++) o[nd][i] = 0.0f;

    // per-thread cp.async chunk coordinates (constant across kt)
    // K tiles: 1024 16B-chunks: row = c>>3 (0..127), col = c&7
    // V tiles: 1024 16B-chunks: d = c>>4 (0..63), col = c&15
    const char* kh_b = (const char*)g_kh + (size_t)bh * SS * DD * 2;
    const char* kl_b = (const char*)g_kl + (size_t)bh * SS * DD * 2;
    const char* vh_b = (const char*)g_vth + (size_t)bh * SS * DD * 2;
    const char* vl_b = (const char*)g_vtl + (size_t)bh * SS * DD * 2;

    for (int kt = 0; kt < 16; kt++) {
        const int n0 = kt * 128;
        __syncthreads();   // previous compute done with smem
        #pragma unroll
        for (int cc = 0; cc < 4; cc++) {
            const int c = tid + cc * 256;
            const int kr = c >> 3, kc = c & 7;          // K chunk
            const int vd = c >> 4, vc = c & 15;         // V chunk
            const size_t ksrc = ((size_t)(n0 + kr) * DD) * 2 + kc * 16;
            const size_t vsrc = ((size_t)vd * SS + n0) * 2 + vc * 16;
            CPA16(sb + SM_KH + kr * 144 + kc * 16, kh_b + ksrc);
            CPA16(sb + SM_KL + kr * 144 + kc * 16, kl_b + ksrc);
            CPA16(sb + SM_VH + vd * 272 + vc * 16, vh_b + vsrc);
            CPA16(sb + SM_VL + vd * 272 + vc * 16, vl_b + vsrc);
        }
        CPA_COMMIT();
        CPA_WAIT0();
        __syncthreads();

        uint4 mg = *(const uint4*)(g_mbits + mb0 + n0 / 32);
        uint4 m8 = *(const uint4*)(g_mbits + mb8 + n0 / 32);
        const uint32_t* mgw = (const uint32_t*)&mg;
        const uint32_t* m8w = (const uint32_t*)&m8;

        #pragma unroll
        for (int h = 0; h < 2; h++) {
            float s[8][4];
            #pragma unroll
            for (int nt = 0; nt < 8; nt++)
                #pragma unroll
                for (int i = 0; i < 4; i++) s[nt][i] = 0.0f;

            #pragma unroll
            for (int ks = 0; ks < 4; ks++) {
                #pragma unroll
                for (int pass = 0; pass < 3; pass++) {
                    const uint32_t* A = (pass == 2) ? ql[ks] : qh[ks];
                    const int bb = (pass == 1) ? SM_KL : SM_KH;
                    #pragma unroll
                    for (int nt = 0; nt < 8; nt++) {
                        const char* ad = smem + bb + ((h * 8 + nt) * 8 + g) * 144 + ks * 32 + t * 4;
                        uint32_t b0 = *(const uint32_t*)ad;
                        uint32_t b1 = *(const uint32_t*)(ad + 16);
                        MMA(s[nt], A, b0, b1);
                    }
                }
            }

            #pragma unroll
            for (int kap = 0; kap < 4; kap++) {
                uint32_t ah[4], al[4];
                #pragma unroll
                for (int i = 0; i < 2; i++) {
                    const int nt  = kap * 2 + i;
                    const int ntg = h * 8 + nt;
                    const uint32_t wg = mgw[ntg >> 2] >> ((ntg & 3) * 8 + t * 2);
                    const uint32_t w8 = m8w[ntg >> 2] >> ((ntg & 3) * 8 + t * 2);
                    const float e0 = (wg      & 1) ? 0.0f : ex2(s[nt][0]);
                    const float e1 = (wg >> 1 & 1) ? 0.0f : ex2(s[nt][1]);
                    const float e2 = (w8      & 1) ? 0.0f : ex2(s[nt][2]);
                    const float e3 = (w8 >> 1 & 1) ? 0.0f : ex2(s[nt][3]);
                    sum_g  += e0 + e1;
                    sum_g8 += e2 + e3;
                    const int c = n0 + ntg * 8 + t * 2;
                    __stcs((float2*)(arow_g  + c), make_float2(e0, e1));
                    __stcs((float2*)(arow_g8 + c), make_float2(e2, e3));
                    pack_hl(e0, e1, ah[i*2+0], al[i*2+0]);
                    pack_hl(e2, e3, ah[i*2+1], al[i*2+1]);
                }
                #pragma unroll
                for (int nd = 0; nd < 8; nd++) {
                    const int vbase = (nd * 8 + g) * 272 + (h * 4 + kap) * 32 + t * 4;
                    const char* vh = smem + SM_VH + vbase;
                    const char* vl = smem + SM_VL + vbase;
                    uint32_t bh0 = *(const uint32_t*)vh;
                    uint32_t bh1 = *(const uint32_t*)(vh + 16);
                    uint32_t bl0 = *(const uint32_t*)vl;
                    uint32_t bl1 = *(const uint32_t*)(vl + 16);
                    MMA(o[nd], ah, bh0, bh1);
                    MMA(o[nd], ah, bl0, bl1);
                    MMA(o[nd], al, bh0, bh1);
                }
            }
        }
    }

    sum_g  += __shfl_xor_sync(0xffffffffu, sum_g, 1);
    sum_g  += __shfl_xor_sync(0xffffffffu, sum_g, 2);
    sum_g8 += __shfl_xor_sync(0xffffffffu, sum_g8, 1);
    sum_g8 += __shfl_xor_sync(0xffffffffu, sum_g8, 2);
    const float inv_g  = 1.0f / sum_g;
    const float inv_g8 = 1.0f / sum_g8;
    if (t == 0) {
        g_row_s[bh * SS + r0] = sum_g;
        g_row_s[bh * SS + r8] = sum_g8;
    }

    float* orow_g  = out + ((size_t)bh * SS + r0) * DD;
    float* orow_g8 = out + ((size_t)bh * SS + r8) * DD;
    #pragma unroll
    for (int nd = 0; nd < 8; nd++) {
        *(float2*)(orow_g  + nd * 8 + t * 2) = make_float2(o[nd][0] * inv_g,  o[nd][1] * inv_g);
        *(float2*)(orow_g8 + nd * 8 + t * 2) = make_float2(o[nd][2] * inv_g8, o[nd][3] * inv_g8);
    }
}

// ---------------------------------------------------------------------------
// Kernel 2: atten[row, :] *= 1/g_row_s[row]
// ---------------------------------------------------------------------------
__global__ void __launch_bounds__(256)
atten_norm(float* __restrict__ atten)
{
    const int row = blockIdx.x;
    const float inv = 1.0f / g_row_s[row];
    float4* p = (float4*)(atten + (size_t)row * SS);
    const int i0 = threadIdx.x;
    float4 a = __ldcs(p + i0);
    float4 c = __ldcs(p + i0 + 256);
    a.x *= inv; a.y *= inv; a.z *= inv; a.w *= inv;
    c.x *= inv; c.y *= inv; c.z *= inv; c.w *= inv;
    __stcs(p + i0, a);
    __stcs(p + i0 + 256, c);
}

// ---------------------------------------------------------------------------
extern "C" void kernel_launch(void* const* d_in, const int* in_sizes, int n_in,
                              void* d_out, int out_size)
{
    const float* q = (const float*)d_in[0];
    const float* k = (const float*)d_in[1];
    const float* v = (const float*)d_in[2];
    const int*   mask = (const int*)d_in[3];

    float* out   = (float*)d_out;                 // [B,H,S,D]
    float* atten = out + (size_t)BH * SS * DD;    // [B,H,S,S]

    cudaFuncSetAttribute(sdpa_flash, cudaFuncAttributeMaxDynamicSharedMemorySize, SMEM_BYTES);

    mask_pack<<<1024, 256>>>(mask);
    conv_k<<<BH * SS * DD / (256 * 8), 256>>>(k);
    conv_vt<<<dim3(SS / 64, BH), 256>>>(v);
    dim3 grid(SS / 128, BH);
    sdpa_flash<<<grid, 256, SMEM_BYTES>>>(q, atten, out);
    atten_norm<<<BH * SS, 256>>>(atten);
    (void)in_sizes; (void)n_in; (void)out_size;
}